// round 6
// baseline (speedup 1.0000x reference)
#include <cuda_runtime.h>
#include <cuda_fp16.h>

#define N_NODES 50000
#define N_EDGES 800000
#define HID 64
#define SCAN_BLOCKS ((N_NODES + 255) / 256)   // 196
#define FILL_BLOCKS ((N_EDGES + 255) / 256)   // 3125
#define AB1_BLOCKS  ((N_NODES + 31) / 32)     // 1563

// ---- scratch (static device globals; zero-initialized at load) ----
__device__ int    g_deg[N_NODES];       // re-zeroed by k_scan23 each call
__device__ int    g_off[N_NODES + 1];
__device__ int    g_rank[N_EDGES];
__device__ int    g_bsum[256];
__device__ int    g_srcidx[N_EDGES];
__device__ float  g_A[N_NODES * HID];
__device__ __half g_Bh[N_NODES * HID];  // B table in fp16
__device__ float  g_H[N_NODES * HID];

typedef unsigned long long ull;

// ---- packed f32x2 helpers (identical .rn rounding to scalar fp32) ----
__device__ __forceinline__ ull pack2(float x, float y) {
    ull r;
    asm("mov.b64 %0, {%1, %2};" : "=l"(r) : "f"(x), "f"(y));
    return r;
}
__device__ __forceinline__ void unpack2(ull v, float& x, float& y) {
    asm("mov.b64 {%0, %1}, %2;" : "=f"(x), "=f"(y) : "l"(v));
}
__device__ __forceinline__ void fma2(ull& acc, ull a, ull b) {
    asm("fma.rn.f32x2 %0, %1, %2, %0;" : "+l"(acc) : "l"(a), "l"(b));
}
__device__ __forceinline__ void add2(ull& a, ull b) {
    asm("add.rn.f32x2 %0, %0, %1;" : "+l"(a) : "l"(b));
}

// ---------------- CSR build ----------------
// single atomic pass: degree histogram AND per-edge rank within its dst bucket
__global__ void k_count(const int* __restrict__ ei) {
    int e = blockIdx.x * blockDim.x + threadIdx.x;
    if (e < N_EDGES) g_rank[e] = atomicAdd(&g_deg[ei[N_EDGES + e]], 1);
}

__global__ void k_scan1() {
    __shared__ int sh[256];
    int tid = threadIdx.x;
    int i = blockIdx.x * 256 + tid;
    int v = (i < N_NODES) ? g_deg[i] : 0;
    sh[tid] = v;
    __syncthreads();
#pragma unroll
    for (int ofs = 1; ofs < 256; ofs <<= 1) {
        int t = (tid >= ofs) ? sh[tid - ofs] : 0;
        __syncthreads();
        sh[tid] += t;
        __syncthreads();
    }
    if (i < N_NODES) g_off[i] = sh[tid] - v;
    if (tid == 255) g_bsum[blockIdx.x] = sh[255];
}

// merged scan2+scan3 + re-zero g_deg for next invocation
__global__ void k_scan23() {
    __shared__ int sh[256];
    int tid = threadIdx.x;
    int v = (tid < SCAN_BLOCKS) ? g_bsum[tid] : 0;
    sh[tid] = v;
    __syncthreads();
#pragma unroll
    for (int ofs = 1; ofs < 256; ofs <<= 1) {
        int t = (tid >= ofs) ? sh[tid - ofs] : 0;
        __syncthreads();
        sh[tid] += t;
        __syncthreads();
    }
    int prefix = (blockIdx.x == 0) ? 0 : sh[blockIdx.x - 1];
    int i = blockIdx.x * 256 + tid;
    if (i < N_NODES) {
        g_off[i] += prefix;
        g_deg[i] = 0;
    }
    if (blockIdx.x == 0 && tid == 0) g_off[N_NODES] = sh[255];
}

// ---------------- merged fill + layer-1 node pre-GEMMs ----------------
// blocks [0, FILL_BLOCKS): atomic-free CSR fill.
// blocks [FILL_BLOCKS, +AB1_BLOCKS): A = x@(Wtop-Wbot)+b, B = x@Wbot (fp16).
__global__ void __launch_bounds__(256) k_fill_ab1(const int* __restrict__ ei,
                                                  const float* __restrict__ x,
                                                  const float* __restrict__ w1a,
                                                  const float* __restrict__ b1a) {
    __shared__ float wd[16 * 64];
    __shared__ float wb[16 * 64];
    __shared__ float bshm[64];
    if (blockIdx.x < FILL_BLOCKS) {
        int e = blockIdx.x * 256 + threadIdx.x;
        if (e < N_EDGES) {
            int dst = ei[N_EDGES + e];
            g_srcidx[g_off[dst] + g_rank[e]] = ei[e];
        }
        return;
    }
    int bid = blockIdx.x - FILL_BLOCKS;
    int tid = threadIdx.x;
    for (int i = tid; i < 16 * 64; i += 256) {
        float top = w1a[i];
        float bot = w1a[16 * 64 + i];
        wd[i] = top - bot;
        wb[i] = bot;
    }
    if (tid < 64) bshm[tid] = b1a[tid];
    __syncthreads();
    int warp = tid >> 5, lane = tid & 31;
    int nbase = (bid * 8 + warp) * 4;
#pragma unroll
    for (int ni = 0; ni < 4; ni++) {
        int node = nbase + ni;
        if (node >= N_NODES) break;
        float xown = (lane < 16) ? x[node * 16 + lane] : 0.f;
        ull A = pack2(bshm[2 * lane], bshm[2 * lane + 1]);
        ull C = 0ULL;
#pragma unroll
        for (int k = 0; k < 16; k++) {
            float xk = __shfl_sync(0xffffffffu, xown, k);
            ull x2 = pack2(xk, xk);
            fma2(A, x2, *(const ull*)&wd[k * 64 + lane * 2]);
            fma2(C, x2, *(const ull*)&wb[k * 64 + lane * 2]);
        }
        float ax, ay, cx, cy;
        unpack2(A, ax, ay);
        unpack2(C, cx, cy);
        *(float2*)&g_A[node * 64 + lane * 2] = make_float2(ax, ay);
        ((__half2*)g_Bh)[node * 32 + lane] = __floats2half2_rn(cx, cy);
    }
}

// ---------------- edge gather + post-GEMM (both layers; FINAL fuses projection)
// Warp = 4 nodes. Lanes split 16/16: lo half = even edges, hi half = odd edges.
// Each lane covers 4 channels (ch 4*(lane&15) .. +3).
template <int FINAL>
__global__ void __launch_bounds__(256) k_gather_t(const float* __restrict__ Wp,
                                                  const float* __restrict__ bp,
                                                  const float* __restrict__ wl,
                                                  const float* __restrict__ bl,
                                                  float* __restrict__ out) {
    __shared__ ull wsh2[32][66];          // [lane][k] = (W[k][2l], W[k][2l+1]); pad 66
    __shared__ ull accdup[8][4][64];      // [warp][node][k] = (v,v) duplicated pair
    __shared__ float bshm[64];
    int tid = threadIdx.x, warp = tid >> 5, lane = tid & 31;
    // transposed weight build: warp w handles k = w, w+8, ...; coalesced 256B reads
    for (int k = warp; k < 64; k += 8) {
        float2 wv = *(const float2*)&Wp[k * 64 + 2 * lane];
        wsh2[lane][k] = pack2(wv.x, wv.y);
    }
    if (tid < 64) bshm[tid] = bp[tid];
    __syncthreads();

    int nbase = (blockIdx.x * 8 + warp) * 4;
    int lane15 = lane & 15;
    int halfsel = lane >> 4;

    int offs[5];
#pragma unroll
    for (int i = 0; i < 5; i++) {
        int idx = nbase + i;
        if (idx > N_NODES) idx = N_NODES;
        offs[i] = g_off[idx];
    }

    // A rows as half2 (4 ch per lane), per node
    __half2 aH[4][2];
#pragma unroll
    for (int ni = 0; ni < 4; ni++) {
        int node = nbase + ni;
        float4 af = make_float4(0.f, 0.f, 0.f, 0.f);
        if (node < N_NODES) af = *(const float4*)&g_A[node * 64 + 4 * lane15];
        aH[ni][0] = __floats2half2_rn(af.x, af.y);
        aH[ni][1] = __floats2half2_rn(af.z, af.w);
    }

    ull acc2[4][2];
#pragma unroll
    for (int ni = 0; ni < 4; ni++) { acc2[ni][0] = 0ULL; acc2[ni][1] = 0ULL; }

    const __half2 h2z = __floats2half2_rn(0.f, 0.f);
    const char* Bbase = (const char*)g_Bh;

#pragma unroll
    for (int ni = 0; ni < 4; ni++) {
        int e0 = offs[ni], e1 = offs[ni + 1];
        for (int e = e0; e < e1; e += 16) {
            int cnt = e1 - e;
            if (cnt > 16) cnt = 16;
            int li = (lane15 < cnt) ? lane15 : (cnt - 1);
            int sIdx = g_srcidx[e + li];
            if (cnt == 16) {
#pragma unroll
                for (int j = 0; j < 8; j++) {
                    int s = __shfl_sync(0xffffffffu, sIdx, 2 * j + halfsel);
                    ull rb = *(const ull*)(Bbase + (size_t)s * 128 + lane15 * 8);
                    union { ull u; __half2 h[2]; } U;
                    U.u = rb;
                    __half2 v0 = __hmax2(__hadd2(aH[ni][0], U.h[0]), h2z);
                    __half2 v1 = __hmax2(__hadd2(aH[ni][1], U.h[1]), h2z);
                    float2 f0 = __half22float2(v0);
                    float2 f1 = __half22float2(v1);
                    add2(acc2[ni][0], pack2(f0.x, f0.y));
                    add2(acc2[ni][1], pack2(f1.x, f1.y));
                }
            } else {
                int jmax = (cnt + 1) >> 1;
                for (int j = 0; j < jmax; j++) {
                    int eo = 2 * j + halfsel;
                    bool valid = eo < cnt;
                    int sel = valid ? eo : (cnt - 1);
                    int s = __shfl_sync(0xffffffffu, sIdx, sel);
                    ull rb = *(const ull*)(Bbase + (size_t)s * 128 + lane15 * 8);
                    union { ull u; __half2 h[2]; } U;
                    U.u = rb;
                    __half2 v0 = __hmax2(__hadd2(aH[ni][0], U.h[0]), h2z);
                    __half2 v1 = __hmax2(__hadd2(aH[ni][1], U.h[1]), h2z);
                    float2 f0 = __half22float2(v0);
                    float2 f1 = __half22float2(v1);
                    if (!valid) { f0.x = 0.f; f0.y = 0.f; f1.x = 0.f; f1.y = 0.f; }
                    add2(acc2[ni][0], pack2(f0.x, f0.y));
                    add2(acc2[ni][1], pack2(f1.x, f1.y));
                }
            }
        }
    }

    // fold lo/hi halves, scale by 1/deg, store duplicated pairs to shared
#pragma unroll
    for (int ni = 0; ni < 4; ni++) {
        float v0, v1, v2, v3;
        unpack2(acc2[ni][0], v0, v1);
        unpack2(acc2[ni][1], v2, v3);
        v0 += __shfl_xor_sync(0xffffffffu, v0, 16);
        v1 += __shfl_xor_sync(0xffffffffu, v1, 16);
        v2 += __shfl_xor_sync(0xffffffffu, v2, 16);
        v3 += __shfl_xor_sync(0xffffffffu, v3, 16);
        int deg = offs[ni + 1] - offs[ni];
        float inv = (deg > 0) ? (1.f / (float)deg) : 0.f;
        v0 *= inv; v1 *= inv; v2 *= inv; v3 *= inv;
        if ((ni >> 1) == halfsel) {
            ull* dst = &accdup[warp][ni][4 * lane15];
            dst[0] = pack2(v0, v0);
            dst[1] = pack2(v1, v1);
            dst[2] = pack2(v2, v2);
            dst[3] = pack2(v3, v3);
        }
    }
    __syncwarp();

    // epilogue GEMM: out[ni][2l,2l+1] = b + sum_k acc[ni][k] * W[k][2l,2l+1]
    ull accOut[4];
    ull binit = pack2(bshm[2 * lane], bshm[2 * lane + 1]);
#pragma unroll
    for (int ni = 0; ni < 4; ni++) accOut[ni] = binit;

#pragma unroll 8
    for (int k = 0; k < 64; k += 2) {
        ulonglong2 wv = *(const ulonglong2*)&wsh2[lane][k];
#pragma unroll
        for (int ni = 0; ni < 4; ni++) {
            ulonglong2 av = *(const ulonglong2*)&accdup[warp][ni][k];
            fma2(accOut[ni], av.x, wv.x);
            fma2(accOut[ni], av.y, wv.y);
        }
    }

    if (FINAL == 0) {
#pragma unroll
        for (int ni = 0; ni < 4; ni++) {
            int node = nbase + ni;
            if (node < N_NODES) {
                int deg = offs[ni + 1] - offs[ni];
                float o0, o1;
                unpack2(accOut[ni], o0, o1);
                if (deg > 0) { o0 = fmaxf(o0, 0.f); o1 = fmaxf(o1, 0.f); }
                else         { o0 = 0.f; o1 = 0.f; }
                *(float2*)&g_H[node * 64 + lane * 2] = make_float2(o0, o1);
            }
        }
    } else {
        float4 w = *(const float4*)&wl[lane * 4];
        float bl0 = bl[0], bl1 = bl[1];
#pragma unroll
        for (int ni = 0; ni < 4; ni++) {
            int node = nbase + ni;
            if (node < N_NODES) {
                int deg = offs[ni + 1] - offs[ni];
                float o0, o1;
                unpack2(accOut[ni], o0, o1);
                if (deg > 0) { o0 = fmaxf(o0, 0.f); o1 = fmaxf(o1, 0.f); }
                else         { o0 = 0.f; o1 = 0.f; }
                float p0 = o0 * w.x + o1 * w.z;
                float p1 = o0 * w.y + o1 * w.w;
#pragma unroll
                for (int ofs = 16; ofs > 0; ofs >>= 1) {
                    p0 += __shfl_xor_sync(0xffffffffu, p0, ofs);
                    p1 += __shfl_xor_sync(0xffffffffu, p1, ofs);
                }
                if (lane == 0) {
                    out[node * 2 + 0] = p0 + bl0;
                    out[node * 2 + 1] = p1 + bl1;
                }
            }
        }
    }
}

// ---------------- layer-2 node pre-GEMMs from H: 8 nodes per warp, f32x2 ----
__global__ void __launch_bounds__(256) k_nodeAB2(const float* __restrict__ w2a,
                                                 const float* __restrict__ b2a) {
    __shared__ float wdb[64 * 32 * 4];
    __shared__ float bshm[64];
    __shared__ float hsh[8][64 * 8];
    int tid = threadIdx.x;
    for (int idx = tid; idx < 64 * 64; idx += 256) {
        int k = idx >> 6, col = idx & 63;
        float top = w2a[idx];
        float bot = w2a[64 * 64 + idx];
        int ln = col >> 1, comp = col & 1;
        wdb[(k * 32 + ln) * 4 + comp]     = top - bot;
        wdb[(k * 32 + ln) * 4 + 2 + comp] = bot;
    }
    if (tid < 64) bshm[tid] = b2a[tid];
    __syncthreads();
    int warp = tid >> 5, lane = tid & 31;
    int nbase = (blockIdx.x * 8 + warp) * 8;

#pragma unroll
    for (int ni = 0; ni < 8; ni++) {
        int node = nbase + ni;
        float2 h = (node < N_NODES) ? *(const float2*)&g_H[node * 64 + lane * 2]
                                    : make_float2(0.f, 0.f);
        hsh[warp][(2 * lane) * 8 + ni]     = h.x;
        hsh[warp][(2 * lane + 1) * 8 + ni] = h.y;
    }
    __syncwarp();

    ull A[8], C[8];
    ull binit = pack2(bshm[2 * lane], bshm[2 * lane + 1]);
#pragma unroll
    for (int ni = 0; ni < 8; ni++) { A[ni] = binit; C[ni] = 0ULL; }

#pragma unroll 4
    for (int k = 0; k < 64; k++) {
        float4 h03 = *(const float4*)&hsh[warp][k * 8];
        float4 h47 = *(const float4*)&hsh[warp][k * 8 + 4];
        const ull* wp = (const ull*)&wdb[(k * 32 + lane) * 4];
        ull wd2 = wp[0], wb2 = wp[1];
        ull hh;
        hh = pack2(h03.x, h03.x); fma2(A[0], hh, wd2); fma2(C[0], hh, wb2);
        hh = pack2(h03.y, h03.y); fma2(A[1], hh, wd2); fma2(C[1], hh, wb2);
        hh = pack2(h03.z, h03.z); fma2(A[2], hh, wd2); fma2(C[2], hh, wb2);
        hh = pack2(h03.w, h03.w); fma2(A[3], hh, wd2); fma2(C[3], hh, wb2);
        hh = pack2(h47.x, h47.x); fma2(A[4], hh, wd2); fma2(C[4], hh, wb2);
        hh = pack2(h47.y, h47.y); fma2(A[5], hh, wd2); fma2(C[5], hh, wb2);
        hh = pack2(h47.z, h47.z); fma2(A[6], hh, wd2); fma2(C[6], hh, wb2);
        hh = pack2(h47.w, h47.w); fma2(A[7], hh, wd2); fma2(C[7], hh, wb2);
    }
#pragma unroll
    for (int ni = 0; ni < 8; ni++) {
        int node = nbase + ni;
        if (node >= N_NODES) break;
        float ax, ay, cx, cy;
        unpack2(A[ni], ax, ay);
        unpack2(C[ni], cx, cy);
        *(float2*)&g_A[node * 64 + lane * 2] = make_float2(ax, ay);
        ((__half2*)g_Bh)[node * 32 + lane] = __floats2half2_rn(cx, cy);
    }
}

extern "C" void kernel_launch(void* const* d_in, const int* in_sizes, int n_in,
                              void* d_out, int out_size) {
    const float* x   = (const float*)d_in[0];
    const int*   ei  = (const int*)d_in[1];   // int32 (JAX default x64 disabled)
    const float* w1a = (const float*)d_in[2];
    const float* b1a = (const float*)d_in[3];
    const float* w1b = (const float*)d_in[4];
    const float* b1b = (const float*)d_in[5];
    const float* w2a = (const float*)d_in[6];
    const float* b2a = (const float*)d_in[7];
    const float* w2b = (const float*)d_in[8];
    const float* b2b = (const float*)d_in[9];
    const float* wl  = (const float*)d_in[10];
    const float* bl  = (const float*)d_in[11];
    float* out = (float*)d_out;

    k_count<<<FILL_BLOCKS, 256>>>(ei);
    k_scan1<<<SCAN_BLOCKS, 256>>>();
    k_scan23<<<SCAN_BLOCKS, 256>>>();
    k_fill_ab1<<<FILL_BLOCKS + AB1_BLOCKS, 256>>>(ei, x, w1a, b1a);

    k_gather_t<0><<<AB1_BLOCKS, 256>>>(w1b, b1b, wl, bl, out);
    k_nodeAB2<<<(N_NODES + 63) / 64, 256>>>(w2a, b2a);
    k_gather_t<1><<<AB1_BLOCKS, 256>>>(w2b, b2b, wl, bl, out);
}

// round 7
// speedup vs baseline: 1.0931x; 1.0931x over previous
#include <cuda_runtime.h>
#include <cuda_fp16.h>

#define N_NODES 50000
#define N_EDGES 800000
#define HID 64
#define SCAN_BLOCKS ((N_NODES + 255) / 256)   // 196

// ---- scratch (static device globals; zero-initialized at load) ----
__device__ int    g_deg[N_NODES];       // re-zeroed by k_scan23 each call
__device__ int    g_off[N_NODES + 1];
__device__ int    g_rank[N_EDGES];
__device__ int    g_bsum[256];
__device__ int    g_srcidx[N_EDGES];
__device__ float  g_A[N_NODES * HID];
__device__ __half g_Bh[N_NODES * HID];  // B table in fp16
__device__ float  g_H[N_NODES * HID];

typedef unsigned long long ull;

// ---- packed f32x2 helpers (identical .rn rounding to scalar fp32) ----
__device__ __forceinline__ ull pack2(float x, float y) {
    ull r;
    asm("mov.b64 %0, {%1, %2};" : "=l"(r) : "f"(x), "f"(y));
    return r;
}
__device__ __forceinline__ void unpack2(ull v, float& x, float& y) {
    asm("mov.b64 {%0, %1}, %2;" : "=f"(x), "=f"(y) : "l"(v));
}
__device__ __forceinline__ void fma2(ull& acc, ull a, ull b) {
    asm("fma.rn.f32x2 %0, %1, %2, %0;" : "+l"(acc) : "l"(a), "l"(b));
}
__device__ __forceinline__ void add2(ull& a, ull b) {
    asm("add.rn.f32x2 %0, %0, %1;" : "+l"(a) : "l"(b));
}

// ---------------- CSR build ----------------
__global__ void k_count(const int* __restrict__ ei) {
    int e = blockIdx.x * blockDim.x + threadIdx.x;
    if (e < N_EDGES) g_rank[e] = atomicAdd(&g_deg[ei[N_EDGES + e]], 1);
}

__global__ void k_scan1() {
    __shared__ int sh[256];
    int tid = threadIdx.x;
    int i = blockIdx.x * 256 + tid;
    int v = (i < N_NODES) ? g_deg[i] : 0;
    sh[tid] = v;
    __syncthreads();
#pragma unroll
    for (int ofs = 1; ofs < 256; ofs <<= 1) {
        int t = (tid >= ofs) ? sh[tid - ofs] : 0;
        __syncthreads();
        sh[tid] += t;
        __syncthreads();
    }
    if (i < N_NODES) g_off[i] = sh[tid] - v;
    if (tid == 255) g_bsum[blockIdx.x] = sh[255];
}

// merged scan2+scan3 + re-zero g_deg for next invocation
__global__ void k_scan23() {
    __shared__ int sh[256];
    int tid = threadIdx.x;
    int v = (tid < SCAN_BLOCKS) ? g_bsum[tid] : 0;
    sh[tid] = v;
    __syncthreads();
#pragma unroll
    for (int ofs = 1; ofs < 256; ofs <<= 1) {
        int t = (tid >= ofs) ? sh[tid - ofs] : 0;
        __syncthreads();
        sh[tid] += t;
        __syncthreads();
    }
    int prefix = (blockIdx.x == 0) ? 0 : sh[blockIdx.x - 1];
    int i = blockIdx.x * 256 + tid;
    if (i < N_NODES) {
        g_off[i] += prefix;
        g_deg[i] = 0;
    }
    if (blockIdx.x == 0 && tid == 0) g_off[N_NODES] = sh[255];
}

// atomic-free fill: position = off[dst] + rank[e]
__global__ void k_fill(const int* __restrict__ ei) {
    int e = blockIdx.x * blockDim.x + threadIdx.x;
    if (e < N_EDGES) {
        int dst = ei[N_EDGES + e];
        g_srcidx[g_off[dst] + g_rank[e]] = ei[e];
    }
}

// ---------------- layer-1 node pre-GEMMs: A = x@(Wtop-Wbot)+b, B = x@Wbot ----
__global__ void __launch_bounds__(256) k_nodeAB1(const float* __restrict__ x,
                                                 const float* __restrict__ w1a,
                                                 const float* __restrict__ b1a) {
    __shared__ float wd[16 * 64];
    __shared__ float wb[16 * 64];
    __shared__ float bshm[64];
    int tid = threadIdx.x;
    for (int i = tid; i < 16 * 64; i += 256) {
        float top = w1a[i];
        float bot = w1a[16 * 64 + i];
        wd[i] = top - bot;
        wb[i] = bot;
    }
    if (tid < 64) bshm[tid] = b1a[tid];
    __syncthreads();
    int warp = tid >> 5, lane = tid & 31;
    int nbase = (blockIdx.x * 8 + warp) * 4;
#pragma unroll
    for (int ni = 0; ni < 4; ni++) {
        int node = nbase + ni;
        if (node >= N_NODES) break;
        float xown = (lane < 16) ? x[node * 16 + lane] : 0.f;
        ull A = pack2(bshm[2 * lane], bshm[2 * lane + 1]);
        ull C = 0ULL;
#pragma unroll
        for (int k = 0; k < 16; k++) {
            float xk = __shfl_sync(0xffffffffu, xown, k);
            ull x2 = pack2(xk, xk);
            fma2(A, x2, *(const ull*)&wd[k * 64 + lane * 2]);
            fma2(C, x2, *(const ull*)&wb[k * 64 + lane * 2]);
        }
        float ax, ay, cx, cy;
        unpack2(A, ax, ay);
        unpack2(C, cx, cy);
        *(float2*)&g_A[node * 64 + lane * 2] = make_float2(ax, ay);
        ((__half2*)g_Bh)[node * 32 + lane] = __floats2half2_rn(cx, cy);
    }
}

// ---------------- edge gather + post-GEMM (both layers; FINAL fuses projection)
// Warp = 4 nodes, 2 channels per lane (R5 layout). Edge math in fp16
// (HADD2+HMAX2+HADD2 partial), partial flushed to f32x2 every <=8 edges.
template <int FINAL>
__global__ void __launch_bounds__(256) k_gather_t(const float* __restrict__ Wp,
                                                  const float* __restrict__ bp,
                                                  const float* __restrict__ wl,
                                                  const float* __restrict__ bl,
                                                  float* __restrict__ out) {
    __shared__ ull wshT[64][32];       // [k][lane] = (W[k][2l], W[k][2l+1]); conflict-free
    __shared__ ull accdup[8][4][64];   // [warp][node][k] = (v,v) duplicated pair
    __shared__ float bshm[64];
    int tid = threadIdx.x, warp = tid >> 5, lane = tid & 31;
    for (int k = warp; k < 64; k += 8) {
        float2 wv = *(const float2*)&Wp[k * 64 + 2 * lane];
        wshT[k][lane] = pack2(wv.x, wv.y);
    }
    if (tid < 64) bshm[tid] = bp[tid];
    __syncthreads();

    int nbase = (blockIdx.x * 8 + warp) * 4;
    const __half2* __restrict__ Bh2 = (const __half2*)g_Bh;
    const __half2 h2z = __floats2half2_rn(0.f, 0.f);

    int offs[5];
#pragma unroll
    for (int i = 0; i < 5; i++) {
        int idx = nbase + i;
        if (idx > N_NODES) idx = N_NODES;
        offs[i] = g_off[idx];
    }

#pragma unroll
    for (int ni = 0; ni < 4; ni++) {
        int node = nbase + ni;
        ull acc2 = 0ULL;
        if (node < N_NODES) {
            int e0 = offs[ni], e1 = offs[ni + 1];
            float2 af = *(const float2*)&g_A[node * 64 + lane * 2];
            __half2 aH = __floats2half2_rn(af.x, af.y);
            int e = e0;
            for (; e + 8 <= e1; e += 8) {
                int s[8];
#pragma unroll
                for (int j = 0; j < 8; j++) s[j] = g_srcidx[e + j];
                __half2 b[8];
#pragma unroll
                for (int j = 0; j < 8; j++) b[j] = Bh2[s[j] * 32 + lane];
                __half2 p = __hmax2(__hadd2(aH, b[0]), h2z);
#pragma unroll
                for (int j = 1; j < 8; j++)
                    p = __hadd2(p, __hmax2(__hadd2(aH, b[j]), h2z));
                float2 f = __half22float2(p);
                add2(acc2, pack2(f.x, f.y));
            }
            if (e < e1) {
                __half2 p = h2z;
                for (; e < e1; e++) {
                    __half2 b = Bh2[g_srcidx[e] * 32 + lane];
                    p = __hadd2(p, __hmax2(__hadd2(aH, b), h2z));
                }
                float2 f = __half22float2(p);
                add2(acc2, pack2(f.x, f.y));
            }
        }
        int deg = offs[ni + 1] - offs[ni];
        float v0, v1;
        unpack2(acc2, v0, v1);
        float inv = (deg > 0) ? (1.f / (float)deg) : 0.f;
        v0 *= inv;
        v1 *= inv;
        accdup[warp][ni][2 * lane]     = pack2(v0, v0);
        accdup[warp][ni][2 * lane + 1] = pack2(v1, v1);
    }
    __syncwarp();

    // epilogue GEMM: out[ni][2l,2l+1] = b + sum_k acc[ni][k] * W[k][2l,2l+1]
    ull accOut[4];
    ull binit = pack2(bshm[2 * lane], bshm[2 * lane + 1]);
#pragma unroll
    for (int ni = 0; ni < 4; ni++) accOut[ni] = binit;

#pragma unroll 8
    for (int k = 0; k < 64; k += 2) {
        ull w0 = wshT[k][lane];
        ull w1 = wshT[k + 1][lane];
#pragma unroll
        for (int ni = 0; ni < 4; ni++) {
            ulonglong2 av = *(const ulonglong2*)&accdup[warp][ni][k];
            fma2(accOut[ni], av.x, w0);
            fma2(accOut[ni], av.y, w1);
        }
    }

    if (FINAL == 0) {
#pragma unroll
        for (int ni = 0; ni < 4; ni++) {
            int node = nbase + ni;
            if (node < N_NODES) {
                int deg = offs[ni + 1] - offs[ni];
                float o0, o1;
                unpack2(accOut[ni], o0, o1);
                if (deg > 0) { o0 = fmaxf(o0, 0.f); o1 = fmaxf(o1, 0.f); }
                else         { o0 = 0.f; o1 = 0.f; }
                *(float2*)&g_H[node * 64 + lane * 2] = make_float2(o0, o1);
            }
        }
    } else {
        float4 w = *(const float4*)&wl[lane * 4];
        float bl0 = bl[0], bl1 = bl[1];
#pragma unroll
        for (int ni = 0; ni < 4; ni++) {
            int node = nbase + ni;
            if (node < N_NODES) {
                int deg = offs[ni + 1] - offs[ni];
                float o0, o1;
                unpack2(accOut[ni], o0, o1);
                if (deg > 0) { o0 = fmaxf(o0, 0.f); o1 = fmaxf(o1, 0.f); }
                else         { o0 = 0.f; o1 = 0.f; }
                float p0 = o0 * w.x + o1 * w.z;
                float p1 = o0 * w.y + o1 * w.w;
#pragma unroll
                for (int ofs = 16; ofs > 0; ofs >>= 1) {
                    p0 += __shfl_xor_sync(0xffffffffu, p0, ofs);
                    p1 += __shfl_xor_sync(0xffffffffu, p1, ofs);
                }
                if (lane == 0) {
                    out[node * 2 + 0] = p0 + bl0;
                    out[node * 2 + 1] = p1 + bl1;
                }
            }
        }
    }
}

// ---------------- layer-2 node pre-GEMMs from H: 8 nodes per warp, f32x2 ----
__global__ void __launch_bounds__(256) k_nodeAB2(const float* __restrict__ w2a,
                                                 const float* __restrict__ b2a) {
    __shared__ float wdb[64 * 32 * 4];
    __shared__ float bshm[64];
    __shared__ float hsh[8][64 * 8];
    int tid = threadIdx.x;
    for (int idx = tid; idx < 64 * 64; idx += 256) {
        int k = idx >> 6, col = idx & 63;
        float top = w2a[idx];
        float bot = w2a[64 * 64 + idx];
        int ln = col >> 1, comp = col & 1;
        wdb[(k * 32 + ln) * 4 + comp]     = top - bot;
        wdb[(k * 32 + ln) * 4 + 2 + comp] = bot;
    }
    if (tid < 64) bshm[tid] = b2a[tid];
    __syncthreads();
    int warp = tid >> 5, lane = tid & 31;
    int nbase = (blockIdx.x * 8 + warp) * 8;

#pragma unroll
    for (int ni = 0; ni < 8; ni++) {
        int node = nbase + ni;
        float2 h = (node < N_NODES) ? *(const float2*)&g_H[node * 64 + lane * 2]
                                    : make_float2(0.f, 0.f);
        hsh[warp][(2 * lane) * 8 + ni]     = h.x;
        hsh[warp][(2 * lane + 1) * 8 + ni] = h.y;
    }
    __syncwarp();

    ull A[8], C[8];
    ull binit = pack2(bshm[2 * lane], bshm[2 * lane + 1]);
#pragma unroll
    for (int ni = 0; ni < 8; ni++) { A[ni] = binit; C[ni] = 0ULL; }

#pragma unroll 4
    for (int k = 0; k < 64; k++) {
        float4 h03 = *(const float4*)&hsh[warp][k * 8];
        float4 h47 = *(const float4*)&hsh[warp][k * 8 + 4];
        const ull* wp = (const ull*)&wdb[(k * 32 + lane) * 4];
        ull wd2 = wp[0], wb2 = wp[1];
        ull hh;
        hh = pack2(h03.x, h03.x); fma2(A[0], hh, wd2); fma2(C[0], hh, wb2);
        hh = pack2(h03.y, h03.y); fma2(A[1], hh, wd2); fma2(C[1], hh, wb2);
        hh = pack2(h03.z, h03.z); fma2(A[2], hh, wd2); fma2(C[2], hh, wb2);
        hh = pack2(h03.w, h03.w); fma2(A[3], hh, wd2); fma2(C[3], hh, wb2);
        hh = pack2(h47.x, h47.x); fma2(A[4], hh, wd2); fma2(C[4], hh, wb2);
        hh = pack2(h47.y, h47.y); fma2(A[5], hh, wd2); fma2(C[5], hh, wb2);
        hh = pack2(h47.z, h47.z); fma2(A[6], hh, wd2); fma2(C[6], hh, wb2);
        hh = pack2(h47.w, h47.w); fma2(A[7], hh, wd2); fma2(C[7], hh, wb2);
    }
#pragma unroll
    for (int ni = 0; ni < 8; ni++) {
        int node = nbase + ni;
        if (node >= N_NODES) break;
        float ax, ay, cx, cy;
        unpack2(A[ni], ax, ay);
        unpack2(C[ni], cx, cy);
        *(float2*)&g_A[node * 64 + lane * 2] = make_float2(ax, ay);
        ((__half2*)g_Bh)[node * 32 + lane] = __floats2half2_rn(cx, cy);
    }
}

extern "C" void kernel_launch(void* const* d_in, const int* in_sizes, int n_in,
                              void* d_out, int out_size) {
    const float* x   = (const float*)d_in[0];
    const int*   ei  = (const int*)d_in[1];   // int32 (JAX default x64 disabled)
    const float* w1a = (const float*)d_in[2];
    const float* b1a = (const float*)d_in[3];
    const float* w1b = (const float*)d_in[4];
    const float* b1b = (const float*)d_in[5];
    const float* w2a = (const float*)d_in[6];
    const float* b2a = (const float*)d_in[7];
    const float* w2b = (const float*)d_in[8];
    const float* b2b = (const float*)d_in[9];
    const float* wl  = (const float*)d_in[10];
    const float* bl  = (const float*)d_in[11];
    float* out = (float*)d_out;

    // CSR build: count(+rank) -> scan1 -> scan23(+re-zero deg) -> fill
    k_count<<<(N_EDGES + 255) / 256, 256>>>(ei);
    k_scan1<<<SCAN_BLOCKS, 256>>>();
    k_scan23<<<SCAN_BLOCKS, 256>>>();
    k_fill<<<(N_EDGES + 255) / 256, 256>>>(ei);

    int gather_blocks = (N_NODES + 31) / 32;   // 8 warps x 4 nodes
    int ab2_blocks    = (N_NODES + 63) / 64;   // 8 warps x 8 nodes

    // layer 1
    k_nodeAB1<<<gather_blocks, 256>>>(x, w1a, b1a);
    k_gather_t<0><<<gather_blocks, 256>>>(w1b, b1b, wl, bl, out);

    // layer 2 (+ fused final projection)
    k_nodeAB2<<<ab2_blocks, 256>>>(w2a, b2a);
    k_gather_t<1><<<gather_blocks, 256>>>(w2b, b2b, wl, bl, out);
}

// round 8
// speedup vs baseline: 1.1400x; 1.0430x over previous
#include <cuda_runtime.h>
#include <cuda_fp16.h>

#define N_NODES 50000
#define N_EDGES 800000
#define HID 64
#define SCAN_BLOCKS ((N_NODES + 255) / 256)   // 196
#define EPAIR_BLOCKS ((N_EDGES / 2 + 255) / 256)  // 1563

// ---- scratch (static device globals; zero-initialized at load) ----
__device__ int    g_deg[N_NODES];       // re-zeroed by k_scan23 each call
__device__ int    g_off[N_NODES + 1];
__device__ int    g_rank[N_EDGES];      // packed: (rank << 16) | dst
__device__ int    g_bsum[256];
__device__ int    g_srcidx[N_EDGES];
__device__ float  g_A[N_NODES * HID];
__device__ __half g_Bh[N_NODES * HID];  // B table in fp16
__device__ __half g_Hh[N_NODES * HID];  // H in fp16 (layer-1 output)

typedef unsigned long long ull;

// ---- packed f32x2 helpers (identical .rn rounding to scalar fp32) ----
__device__ __forceinline__ ull pack2(float x, float y) {
    ull r;
    asm("mov.b64 %0, {%1, %2};" : "=l"(r) : "f"(x), "f"(y));
    return r;
}
__device__ __forceinline__ void unpack2(ull v, float& x, float& y) {
    asm("mov.b64 {%0, %1}, %2;" : "=f"(x), "=f"(y) : "l"(v));
}
__device__ __forceinline__ void fma2(ull& acc, ull a, ull b) {
    asm("fma.rn.f32x2 %0, %1, %2, %0;" : "+l"(acc) : "l"(a), "l"(b));
}

// ---------------- CSR build ----------------
// vectorized single atomic pass: degree histogram + packed (rank|dst) per edge
__global__ void k_count(const int* __restrict__ ei) {
    int t = blockIdx.x * blockDim.x + threadIdx.x;
    int e = 2 * t;
    if (e + 1 < N_EDGES) {
        int2 d = *(const int2*)&ei[N_EDGES + e];
        int r0 = atomicAdd(&g_deg[d.x], 1);
        int r1 = atomicAdd(&g_deg[d.y], 1);
        *(int2*)&g_rank[e] = make_int2((r0 << 16) | d.x, (r1 << 16) | d.y);
    } else if (e < N_EDGES) {
        int dst = ei[N_EDGES + e];
        int r = atomicAdd(&g_deg[dst], 1);
        g_rank[e] = (r << 16) | dst;
    }
}

__global__ void k_scan1() {
    __shared__ int sh[256];
    int tid = threadIdx.x;
    int i = blockIdx.x * 256 + tid;
    int v = (i < N_NODES) ? g_deg[i] : 0;
    sh[tid] = v;
    __syncthreads();
#pragma unroll
    for (int ofs = 1; ofs < 256; ofs <<= 1) {
        int t = (tid >= ofs) ? sh[tid - ofs] : 0;
        __syncthreads();
        sh[tid] += t;
        __syncthreads();
    }
    if (i < N_NODES) g_off[i] = sh[tid] - v;
    if (tid == 255) g_bsum[blockIdx.x] = sh[255];
}

// merged scan2+scan3 + re-zero g_deg for next invocation
__global__ void k_scan23() {
    __shared__ int sh[256];
    int tid = threadIdx.x;
    int v = (tid < SCAN_BLOCKS) ? g_bsum[tid] : 0;
    sh[tid] = v;
    __syncthreads();
#pragma unroll
    for (int ofs = 1; ofs < 256; ofs <<= 1) {
        int t = (tid >= ofs) ? sh[tid - ofs] : 0;
        __syncthreads();
        sh[tid] += t;
        __syncthreads();
    }
    int prefix = (blockIdx.x == 0) ? 0 : sh[blockIdx.x - 1];
    int i = blockIdx.x * 256 + tid;
    if (i < N_NODES) {
        g_off[i] += prefix;
        g_deg[i] = 0;
    }
    if (blockIdx.x == 0 && tid == 0) g_off[N_NODES] = sh[255];
}

// atomic-free fill from packed rank|dst: position = off[dst] + rank
__global__ void k_fill(const int* __restrict__ ei) {
    int t = blockIdx.x * blockDim.x + threadIdx.x;
    int e = 2 * t;
    if (e + 1 < N_EDGES) {
        int2 r = *(const int2*)&g_rank[e];
        int2 s = *(const int2*)&ei[e];
        g_srcidx[g_off[r.x & 0xFFFF] + (r.x >> 16)] = s.x;
        g_srcidx[g_off[r.y & 0xFFFF] + (r.y >> 16)] = s.y;
    } else if (e < N_EDGES) {
        int r = g_rank[e];
        g_srcidx[g_off[r & 0xFFFF] + (r >> 16)] = ei[e];
    }
}

// ---------------- layer-1 node pre-GEMMs: A = x@(Wtop-Wbot)+b, B = x@Wbot ----
__global__ void __launch_bounds__(256) k_nodeAB1(const float* __restrict__ x,
                                                 const float* __restrict__ w1a,
                                                 const float* __restrict__ b1a) {
    __shared__ float wd[16 * 64];
    __shared__ float wb[16 * 64];
    __shared__ float bshm[64];
    int tid = threadIdx.x;
    for (int i = tid; i < 16 * 64; i += 256) {
        float top = w1a[i];
        float bot = w1a[16 * 64 + i];
        wd[i] = top - bot;
        wb[i] = bot;
    }
    if (tid < 64) bshm[tid] = b1a[tid];
    __syncthreads();
    int warp = tid >> 5, lane = tid & 31;
    int nbase = (blockIdx.x * 8 + warp) * 4;
#pragma unroll
    for (int ni = 0; ni < 4; ni++) {
        int node = nbase + ni;
        if (node >= N_NODES) break;
        float xown = (lane < 16) ? x[node * 16 + lane] : 0.f;
        ull A = pack2(bshm[2 * lane], bshm[2 * lane + 1]);
        ull C = 0ULL;
#pragma unroll
        for (int k = 0; k < 16; k++) {
            float xk = __shfl_sync(0xffffffffu, xown, k);
            ull x2 = pack2(xk, xk);
            fma2(A, x2, *(const ull*)&wd[k * 64 + lane * 2]);
            fma2(C, x2, *(const ull*)&wb[k * 64 + lane * 2]);
        }
        float ax, ay, cx, cy;
        unpack2(A, ax, ay);
        unpack2(C, cx, cy);
        *(float2*)&g_A[node * 64 + lane * 2] = make_float2(ax, ay);
        ((__half2*)g_Bh)[node * 32 + lane] = __floats2half2_rn(cx, cy);
    }
}

// ---------------- edge gather + post-GEMM (both layers; FINAL fuses projection)
// per node i: acc = mean_e relu(A[i] + B[src_e]); h = relu(acc@Wp + bp)
// (R5-proven structure: MLP=8 fp32 edge loop, pack-based epilogue)
template <int FINAL>
__global__ void __launch_bounds__(256) k_gather_t(const float* __restrict__ Wp,
                                                  const float* __restrict__ bp,
                                                  const float* __restrict__ wl,
                                                  const float* __restrict__ bl,
                                                  float* __restrict__ out) {
    __shared__ float wsh[64 * 64];
    __shared__ float bshm[64];
    __shared__ float accsh[8][64][4];   // [warp][channel][node-in-warp]
    int tid = threadIdx.x;
    for (int i = tid; i < 64 * 64; i += 256) wsh[i] = Wp[i];
    if (tid < 64) bshm[tid] = bp[tid];
    __syncthreads();
    int warp = tid >> 5, lane = tid & 31;
    int nbase = (blockIdx.x * 8 + warp) * 4;
    const __half2* __restrict__ Bh2 = (const __half2*)g_Bh;

    int dg[4];
#pragma unroll
    for (int ni = 0; ni < 4; ni++) {
        int node = nbase + ni;
        float acc0 = 0.f, acc1 = 0.f;
        int deg = 0;
        if (node < N_NODES) {
            int e0 = g_off[node], e1 = g_off[node + 1];
            deg = e1 - e0;
            float2 a = *(const float2*)&g_A[node * 64 + lane * 2];
            int e = e0;
            for (; e + 8 <= e1; e += 8) {
                int s[8];
#pragma unroll
                for (int j = 0; j < 8; j++) s[j] = g_srcidx[e + j];
                float2 b[8];
#pragma unroll
                for (int j = 0; j < 8; j++) b[j] = __half22float2(Bh2[s[j] * 32 + lane]);
#pragma unroll
                for (int j = 0; j < 8; j++) {
                    acc0 += fmaxf(a.x + b[j].x, 0.f);
                    acc1 += fmaxf(a.y + b[j].y, 0.f);
                }
            }
            if (e + 4 <= e1) {
                int s[4];
#pragma unroll
                for (int j = 0; j < 4; j++) s[j] = g_srcidx[e + j];
                float2 b[4];
#pragma unroll
                for (int j = 0; j < 4; j++) b[j] = __half22float2(Bh2[s[j] * 32 + lane]);
#pragma unroll
                for (int j = 0; j < 4; j++) {
                    acc0 += fmaxf(a.x + b[j].x, 0.f);
                    acc1 += fmaxf(a.y + b[j].y, 0.f);
                }
                e += 4;
            }
            for (; e < e1; e++) {
                int s = g_srcidx[e];
                float2 bb = __half22float2(Bh2[s * 32 + lane]);
                acc0 += fmaxf(a.x + bb.x, 0.f);
                acc1 += fmaxf(a.y + bb.y, 0.f);
            }
            if (deg > 0) {
                float inv = 1.0f / (float)deg;
                acc0 *= inv;
                acc1 *= inv;
            }
        }
        dg[ni] = deg;
        accsh[warp][2 * lane][ni] = acc0;
        accsh[warp][2 * lane + 1][ni] = acc1;
    }
    __syncwarp();

    // fused 4-node epilogue GEMM in packed f32x2
    ull accA[4];
    {
        ull binit = pack2(bshm[2 * lane], bshm[2 * lane + 1]);
#pragma unroll
        for (int ni = 0; ni < 4; ni++) accA[ni] = binit;
    }
#pragma unroll 8
    for (int k = 0; k < 64; k++) {
        float4 av = *(const float4*)&accsh[warp][k][0];
        ull w2 = *(const ull*)&wsh[k * 64 + 2 * lane];
        fma2(accA[0], pack2(av.x, av.x), w2);
        fma2(accA[1], pack2(av.y, av.y), w2);
        fma2(accA[2], pack2(av.z, av.z), w2);
        fma2(accA[3], pack2(av.w, av.w), w2);
    }

    if (FINAL == 0) {
#pragma unroll
        for (int ni = 0; ni < 4; ni++) {
            int node = nbase + ni;
            if (node >= N_NODES) break;
            float o0, o1;
            unpack2(accA[ni], o0, o1);
            if (dg[ni] > 0) { o0 = fmaxf(o0, 0.f); o1 = fmaxf(o1, 0.f); }
            else            { o0 = 0.f; o1 = 0.f; }
            ((__half2*)g_Hh)[node * 32 + lane] = __floats2half2_rn(o0, o1);
        }
    } else {
        float4 w = *(const float4*)&wl[lane * 4];
        float bl0 = bl[0], bl1 = bl[1];
#pragma unroll
        for (int ni = 0; ni < 4; ni++) {
            int node = nbase + ni;
            if (node >= N_NODES) break;
            float o0, o1;
            unpack2(accA[ni], o0, o1);
            if (dg[ni] > 0) { o0 = fmaxf(o0, 0.f); o1 = fmaxf(o1, 0.f); }
            else            { o0 = 0.f; o1 = 0.f; }
            float p0 = o0 * w.x + o1 * w.z;
            float p1 = o0 * w.y + o1 * w.w;
#pragma unroll
            for (int ofs = 16; ofs > 0; ofs >>= 1) {
                p0 += __shfl_xor_sync(0xffffffffu, p0, ofs);
                p1 += __shfl_xor_sync(0xffffffffu, p1, ofs);
            }
            if (lane == 0) {
                out[node * 2 + 0] = p0 + bl0;
                out[node * 2 + 1] = p1 + bl1;
            }
        }
    }
}

// ---------------- layer-2 node pre-GEMMs from H(fp16): 8 nodes/warp, f32x2 ---
__global__ void __launch_bounds__(256) k_nodeAB2(const float* __restrict__ w2a,
                                                 const float* __restrict__ b2a) {
    __shared__ float wdb[64 * 32 * 4];
    __shared__ float bshm[64];
    __shared__ float hsh[8][64 * 8];
    int tid = threadIdx.x;
    for (int idx = tid; idx < 64 * 64; idx += 256) {
        int k = idx >> 6, col = idx & 63;
        float top = w2a[idx];
        float bot = w2a[64 * 64 + idx];
        int ln = col >> 1, comp = col & 1;
        wdb[(k * 32 + ln) * 4 + comp]     = top - bot;
        wdb[(k * 32 + ln) * 4 + 2 + comp] = bot;
    }
    if (tid < 64) bshm[tid] = b2a[tid];
    __syncthreads();
    int warp = tid >> 5, lane = tid & 31;
    int nbase = (blockIdx.x * 8 + warp) * 8;
    const __half2* __restrict__ Hh2 = (const __half2*)g_Hh;

#pragma unroll
    for (int ni = 0; ni < 8; ni++) {
        int node = nbase + ni;
        float2 h = (node < N_NODES) ? __half22float2(Hh2[node * 32 + lane])
                                    : make_float2(0.f, 0.f);
        hsh[warp][(2 * lane) * 8 + ni]     = h.x;
        hsh[warp][(2 * lane + 1) * 8 + ni] = h.y;
    }
    __syncwarp();

    ull A[8], C[8];
    ull binit = pack2(bshm[2 * lane], bshm[2 * lane + 1]);
#pragma unroll
    for (int ni = 0; ni < 8; ni++) { A[ni] = binit; C[ni] = 0ULL; }

#pragma unroll 4
    for (int k = 0; k < 64; k++) {
        float4 h03 = *(const float4*)&hsh[warp][k * 8];
        float4 h47 = *(const float4*)&hsh[warp][k * 8 + 4];
        const ull* wp = (const ull*)&wdb[(k * 32 + lane) * 4];
        ull wd2 = wp[0], wb2 = wp[1];
        ull hh;
        hh = pack2(h03.x, h03.x); fma2(A[0], hh, wd2); fma2(C[0], hh, wb2);
        hh = pack2(h03.y, h03.y); fma2(A[1], hh, wd2); fma2(C[1], hh, wb2);
        hh = pack2(h03.z, h03.z); fma2(A[2], hh, wd2); fma2(C[2], hh, wb2);
        hh = pack2(h03.w, h03.w); fma2(A[3], hh, wd2); fma2(C[3], hh, wb2);
        hh = pack2(h47.x, h47.x); fma2(A[4], hh, wd2); fma2(C[4], hh, wb2);
        hh = pack2(h47.y, h47.y); fma2(A[5], hh, wd2); fma2(C[5], hh, wb2);
        hh = pack2(h47.z, h47.z); fma2(A[6], hh, wd2); fma2(C[6], hh, wb2);
        hh = pack2(h47.w, h47.w); fma2(A[7], hh, wd2); fma2(C[7], hh, wb2);
    }
#pragma unroll
    for (int ni = 0; ni < 8; ni++) {
        int node = nbase + ni;
        if (node >= N_NODES) break;
        float ax, ay, cx, cy;
        unpack2(A[ni], ax, ay);
        unpack2(C[ni], cx, cy);
        *(float2*)&g_A[node * 64 + lane * 2] = make_float2(ax, ay);
        ((__half2*)g_Bh)[node * 32 + lane] = __floats2half2_rn(cx, cy);
    }
}

extern "C" void kernel_launch(void* const* d_in, const int* in_sizes, int n_in,
                              void* d_out, int out_size) {
    const float* x   = (const float*)d_in[0];
    const int*   ei  = (const int*)d_in[1];   // int32 (JAX default x64 disabled)
    const float* w1a = (const float*)d_in[2];
    const float* b1a = (const float*)d_in[3];
    const float* w1b = (const float*)d_in[4];
    const float* b1b = (const float*)d_in[5];
    const float* w2a = (const float*)d_in[6];
    const float* b2a = (const float*)d_in[7];
    const float* w2b = (const float*)d_in[8];
    const float* b2b = (const float*)d_in[9];
    const float* wl  = (const float*)d_in[10];
    const float* bl  = (const float*)d_in[11];
    float* out = (float*)d_out;

    // CSR build: count(+packed rank) -> scan1 -> scan23(+re-zero deg) -> fill
    k_count<<<EPAIR_BLOCKS, 256>>>(ei);
    k_scan1<<<SCAN_BLOCKS, 256>>>();
    k_scan23<<<SCAN_BLOCKS, 256>>>();
    k_fill<<<EPAIR_BLOCKS, 256>>>(ei);

    int gather_blocks = (N_NODES + 31) / 32;   // 8 warps x 4 nodes
    int ab2_blocks    = (N_NODES + 63) / 64;   // 8 warps x 8 nodes

    // layer 1
    k_nodeAB1<<<gather_blocks, 256>>>(x, w1a, b1a);
    k_gather_t<0><<<gather_blocks, 256>>>(w1b, b1b, wl, bl, out);

    // layer 2 (+ fused final projection)
    k_nodeAB2<<<ab2_blocks, 256>>>(w2a, b2a);
    k_gather_t<1><<<gather_blocks, 256>>>(w2b, b2b, wl, bl, out);
}